// round 5
// baseline (speedup 1.0000x reference)
#include <cuda_runtime.h>
#include <cstdint>

#define NB 8      // batch
#define NP 3249   // grid points
#define NS 128    // axon segments
#define NE 60     // electrodes
#define THREADS 256
#define NBLOCKS 148
#define SLOTS 2                        // 128-thread slots per block
#define NSLOTS (NBLOCKS * SLOTS)       // 296
#define STAGES 3
#define TILE_FLOATS (NS * NE)          // 7680
#define TILE_BYTES (TILE_FLOATS * 4)   // 30720

#define SMEM_TILES_FLOATS (SLOTS * STAGES * TILE_FLOATS)
#define RED_FLOATS (SLOTS * 4 * 2 * NB)    // [slot][warp][a|v][b]
#define SMEM_BYTES (SMEM_TILES_FLOATS * 4 + NE * NB * 4 + SLOTS * STAGES * 8 + RED_FLOATS * 4 + 128)

__device__ __forceinline__ unsigned long long dup2(float x) {
    unsigned long long r;
    asm("mov.b64 %0, {%1, %1};" : "=l"(r) : "f"(x));
    return r;
}
__device__ __forceinline__ void fma2(unsigned long long& d,
                                     unsigned long long a,
                                     unsigned long long b) {
    asm("fma.rn.f32x2 %0, %1, %2, %0;" : "+l"(d) : "l"(a), "l"(b));
}

__device__ __forceinline__ void mbar_wait(uint32_t addr, uint32_t parity) {
    uint32_t done;
    asm volatile("{\n\t.reg .pred p;\n\t"
                 "mbarrier.try_wait.parity.acquire.cta.shared::cta.b64 p, [%1], %2;\n\t"
                 "selp.b32 %0, 1, 0, p;\n\t}"
                 : "=r"(done) : "r"(addr), "r"(parity) : "memory");
    while (!done) {
        asm volatile("{\n\t.reg .pred p;\n\t"
                     "mbarrier.try_wait.parity.acquire.cta.shared::cta.b64 p, [%1], %2, 0x989680;\n\t"
                     "selp.b32 %0, 1, 0, p;\n\t}"
                     : "=r"(done) : "r"(addr), "r"(parity) : "memory");
    }
}

// Persistent: 148 blocks x 256 threads. Two independent 128-thread slots per
// block (each slot's 4 warps cover all 4 SMSPs, 2 warps/SMSP total). Each
// slot streams its points through a 3-stage cp.async.bulk ring. One thread
// per segment row; 8 batches as 4 packed f32x2 accumulators.
__global__ __launch_bounds__(THREADS, 1)
void axon_map_kernel(const float* __restrict__ amp,
                     const float* __restrict__ pexp,
                     float* __restrict__ out) {
    extern __shared__ __align__(128) char smem_raw[];
    float* tiles = reinterpret_cast<float*>(smem_raw);                 // [SLOTS][STAGES][7680]
    float* ampt  = tiles + SMEM_TILES_FLOATS;                          // [NE][NB]
    unsigned long long* mbar =
        reinterpret_cast<unsigned long long*>(ampt + NE * NB);         // [SLOTS][STAGES]
    float* red   = reinterpret_cast<float*>(mbar + SLOTS * STAGES);    // [SLOTS][4][2][NB]

    const int tid    = threadIdx.x;
    const int slot   = tid >> 7;        // 0 or 1
    const int tid128 = tid & 127;
    const int gslot  = blockIdx.x * SLOTS + slot;

    if (tid < SLOTS * STAGES) {
        const uint32_t a = (uint32_t)__cvta_generic_to_shared(&mbar[tid]);
        asm volatile("mbarrier.init.shared.b64 [%0], 1;" :: "r"(a) : "memory");
    }
    for (int i = tid; i < NB * NE; i += THREADS) {
        const int b = i / NE, e = i % NE;
        ampt[e * NB + b] = amp[i];
    }
    __syncthreads();

    uint32_t stage_tile_addr[STAGES], stage_mbar_addr[STAGES];
    const float* stage_tile[STAGES];
    #pragma unroll
    for (int s = 0; s < STAGES; s++) {
        stage_tile[s] = tiles + (slot * STAGES + s) * TILE_FLOATS;
        stage_tile_addr[s] = (uint32_t)__cvta_generic_to_shared(stage_tile[s]);
        stage_mbar_addr[s] = (uint32_t)__cvta_generic_to_shared(&mbar[slot * STAGES + s]);
    }

    // Prologue: fill all 3 stages.
    if (tid128 == 0) {
        #pragma unroll
        for (int s = 0; s < STAGES; s++) {
            const int p = gslot + s * NSLOTS;
            if (p < NP) {
                asm volatile("mbarrier.arrive.expect_tx.shared.b64 _, [%0], %1;"
                             :: "r"(stage_mbar_addr[s]), "r"((uint32_t)TILE_BYTES) : "memory");
                asm volatile("cp.async.bulk.shared::cluster.global.mbarrier::complete_tx::bytes "
                             "[%0], [%1], %2, [%3];"
                             :: "r"(stage_tile_addr[s]),
                                "l"(pexp + (size_t)p * TILE_FLOATS),
                                "r"((uint32_t)TILE_BYTES), "r"(stage_mbar_addr[s])
                             : "memory");
            }
        }
    }

    const int warp = tid128 >> 5;       // 0..3 within slot
    const int lane = tid128 & 31;
    const int bar_id = slot + 1;        // named barrier per 128-thread slot
    float* red_a = red + slot * (4 * 2 * NB);            // [warp][b]
    float* red_v = red_a + 4 * NB;
    uint32_t ph[STAGES] = {0u, 0u, 0u};
    int st = 0;

    for (int p = gslot; p < NP; p += NSLOTS) {
        mbar_wait(stage_mbar_addr[st], ph[st]);
        ph[st] ^= 1u;

        const float* row = stage_tile[st] + tid128 * NE;

        unsigned long long acc[4];
        #pragma unroll
        for (int q = 0; q < 4; q++) acc[q] = 0ull;

        #pragma unroll
        for (int j = 0; j < NE / 4; j++) {
            const float4 r = *reinterpret_cast<const float4*>(row + 4 * j);
            const float re[4] = {r.x, r.y, r.z, r.w};
            #pragma unroll
            for (int k = 0; k < 4; k++) {
                const int e = 4 * j + k;
                const ulonglong2 alo = *reinterpret_cast<const ulonglong2*>(ampt + e * NB);
                const ulonglong2 ahi = *reinterpret_cast<const ulonglong2*>(ampt + e * NB + 4);
                const unsigned long long d = dup2(re[k]);
                fma2(acc[0], d, alo.x);
                fma2(acc[1], d, alo.y);
                fma2(acc[2], d, ahi.x);
                fma2(acc[3], d, ahi.y);
            }
        }

        // Tile fully consumed by this slot -> refill this stage ASAP,
        // overlapping the TMA with the reduction below.
        asm volatile("bar.sync %0, %1;" :: "r"(bar_id), "r"(128) : "memory");
        const int pn = p + STAGES * NSLOTS;
        if (tid128 == 0 && pn < NP) {
            asm volatile("mbarrier.arrive.expect_tx.shared.b64 _, [%0], %1;"
                         :: "r"(stage_mbar_addr[st]), "r"((uint32_t)TILE_BYTES) : "memory");
            asm volatile("cp.async.bulk.shared::cluster.global.mbarrier::complete_tx::bytes "
                         "[%0], [%1], %2, [%3];"
                         :: "r"(stage_tile_addr[st]),
                            "l"(pexp + (size_t)pn * TILE_FLOATS),
                            "r"((uint32_t)TILE_BYTES), "r"(stage_mbar_addr[st])
                         : "memory");
        }

        // abs-argmax over 128 segments per batch: warp shuffle then 4-warp merge.
        #pragma unroll
        for (int b = 0; b < NB; b++) {
            const unsigned long long pa = acc[b >> 1];
            const float v = __uint_as_float((b & 1) ? (uint32_t)(pa >> 32) : (uint32_t)pa);
            float bv = v, ba = fabsf(v);
            #pragma unroll
            for (int off = 16; off > 0; off >>= 1) {
                const float oa = __shfl_xor_sync(0xffffffffu, ba, off);
                const float ov = __shfl_xor_sync(0xffffffffu, bv, off);
                if (oa > ba) { ba = oa; bv = ov; }
            }
            if (lane == 0) { red_a[warp * NB + b] = ba; red_v[warp * NB + b] = bv; }
        }
        asm volatile("bar.sync %0, %1;" :: "r"(bar_id), "r"(128) : "memory");

        if (tid128 < NB) {
            float ba = red_a[tid128];
            float bv = red_v[tid128];
            #pragma unroll
            for (int w = 1; w < 4; w++) {
                if (red_a[w * NB + tid128] > ba) {
                    ba = red_a[w * NB + tid128];
                    bv = red_v[w * NB + tid128];
                }
            }
            out[tid128 * NP + p] = bv;   // threshold |v|>0 is identity
        }

        st = (st == STAGES - 1) ? 0 : st + 1;
    }
}

extern "C" void kernel_launch(void* const* d_in, const int* in_sizes, int n_in,
                              void* d_out, int out_size) {
    (void)n_in; (void)out_size;
    const float* a0 = (const float*)d_in[0];
    const float* a1 = (const float*)d_in[1];
    const float* amp  = a0;
    const float* pexp = a1;
    if (in_sizes[0] != NB * NE) { amp = a1; pexp = a0; }

    cudaFuncSetAttribute(axon_map_kernel,
                         cudaFuncAttributeMaxDynamicSharedMemorySize, SMEM_BYTES);
    axon_map_kernel<<<NBLOCKS, THREADS, SMEM_BYTES>>>(amp, pexp, (float*)d_out);
}

// round 9
// speedup vs baseline: 1.6672x; 1.6672x over previous
#include <cuda_runtime.h>
#include <cstdint>

#define NB 8      // batch
#define NP 3249   // grid points
#define NS 128    // axon segments
#define NE 60     // electrodes
#define NWARPS 7
#define THREADS (NWARPS * 32)          // 224
#define NBLOCKS 148
#define TILE_FLOATS (NS * NE)          // 7680
#define TILE_BYTES (TILE_FLOATS * 4)   // 30720

#define SMEM_BYTES (NWARPS * TILE_BYTES + NE * NB * 4 + NWARPS * 8 + 64)

__device__ __forceinline__ unsigned long long dup2(float x) {
    unsigned long long r;
    asm("mov.b64 %0, {%1, %1};" : "=l"(r) : "f"(x));
    return r;
}
__device__ __forceinline__ void fma2(unsigned long long& d,
                                     unsigned long long a,
                                     unsigned long long b) {
    asm("fma.rn.f32x2 %0, %1, %2, %0;" : "+l"(d) : "l"(a), "l"(b));
}

__device__ __forceinline__ void mbar_wait(uint32_t addr, uint32_t parity) {
    uint32_t done;
    asm volatile("{\n\t.reg .pred p;\n\t"
                 "mbarrier.try_wait.parity.acquire.cta.shared::cta.b64 p, [%1], %2;\n\t"
                 "selp.b32 %0, 1, 0, p;\n\t}"
                 : "=r"(done) : "r"(addr), "r"(parity) : "memory");
    while (!done) {
        asm volatile("{\n\t.reg .pred p;\n\t"
                     "mbarrier.try_wait.parity.acquire.cta.shared::cta.b64 p, [%1], %2, 0x989680;\n\t"
                     "selp.b32 %0, 1, 0, p;\n\t}"
                     : "=r"(done) : "r"(addr), "r"(parity) : "memory");
    }
}

__device__ __forceinline__ void tma_fill(uint32_t tile_addr, uint32_t mbar_addr,
                                         const float* src) {
    asm volatile("mbarrier.arrive.expect_tx.shared.b64 _, [%0], %1;"
                 :: "r"(mbar_addr), "r"((uint32_t)TILE_BYTES) : "memory");
    asm volatile("cp.async.bulk.shared::cluster.global.mbarrier::complete_tx::bytes "
                 "[%0], [%1], %2, [%3];"
                 :: "r"(tile_addr), "l"(src), "r"((uint32_t)TILE_BYTES), "r"(mbar_addr)
                 : "memory");
}

// Persistent: 148 blocks x 224 threads (7 warps). Each warp owns ONE private
// tile stage + mbarrier: it waits, computes its point, then refills its own
// stage for its next point (i += 7). Waiter == refiller, so mbarrier parity
// strictly alternates with the warp's own consumption — no cross-warp phase
// aliasing (the bug that crashed the shared-ring variants). Each warp owns a
// whole point: 4 segment rows/thread (amp broadcast LDS amortized 4x), and
// the abs-argmax is a pure warp-shuffle reduction — zero block-level syncs.
__global__ __launch_bounds__(THREADS, 1)
void axon_map_kernel(const float* __restrict__ amp,
                     const float* __restrict__ pexp,
                     float* __restrict__ out) {
    extern __shared__ __align__(128) char smem_raw[];
    float* tiles = reinterpret_cast<float*>(smem_raw);              // [NWARPS][7680]
    float* ampt  = tiles + NWARPS * TILE_FLOATS;                    // [NE][NB]
    unsigned long long* mbar =
        reinterpret_cast<unsigned long long*>(ampt + NE * NB);      // [NWARPS]

    const int tid  = threadIdx.x;
    const int warp = tid >> 5;
    const int lane = tid & 31;
    const int bid  = blockIdx.x;

    const uint32_t my_tile_addr =
        (uint32_t)__cvta_generic_to_shared(tiles + warp * TILE_FLOATS);
    const uint32_t my_mbar_addr =
        (uint32_t)__cvta_generic_to_shared(&mbar[warp]);

    if (tid < NWARPS) {
        const uint32_t a = (uint32_t)__cvta_generic_to_shared(&mbar[tid]);
        asm volatile("mbarrier.init.shared.b64 [%0], 1;" :: "r"(a) : "memory");
    }
    for (int i = tid; i < NB * NE; i += THREADS) {
        const int b = i / NE, e = i % NE;
        ampt[e * NB + b] = amp[i];
    }
    __syncthreads();

    const float* tile = tiles + warp * TILE_FLOATS;

    // Prologue: each warp fills its own stage for its first point.
    // (bid <= 147, warp <= 6 -> first p <= 1035 < NP, always valid)
    if (lane == 0)
        tma_fill(my_tile_addr, my_mbar_addr,
                 pexp + (size_t)(bid + NBLOCKS * warp) * TILE_FLOATS);

    uint32_t parity = 0;
    for (int p = bid + NBLOCKS * warp; p < NP; p += NBLOCKS * NWARPS) {
        mbar_wait(my_mbar_addr, parity);
        parity ^= 1u;

        unsigned long long acc[4][4];   // [row r][batch pair q]
        #pragma unroll
        for (int r = 0; r < 4; r++)
            #pragma unroll
            for (int q = 0; q < 4; q++) acc[r][q] = 0ull;

        #pragma unroll
        for (int j = 0; j < NE / 4; j++) {
            float4 pe[4];
            #pragma unroll
            for (int r = 0; r < 4; r++)
                pe[r] = *reinterpret_cast<const float4*>(tile + (lane + 32 * r) * NE + 4 * j);
            #pragma unroll
            for (int k = 0; k < 4; k++) {
                const int e = 4 * j + k;
                const ulonglong2 alo = *reinterpret_cast<const ulonglong2*>(ampt + e * NB);
                const ulonglong2 ahi = *reinterpret_cast<const ulonglong2*>(ampt + e * NB + 4);
                #pragma unroll
                for (int r = 0; r < 4; r++) {
                    const float pv = (k == 0) ? pe[r].x : (k == 1) ? pe[r].y
                                   : (k == 2) ? pe[r].z : pe[r].w;
                    const unsigned long long d = dup2(pv);
                    fma2(acc[r][0], d, alo.x);
                    fma2(acc[r][1], d, alo.y);
                    fma2(acc[r][2], d, ahi.x);
                    fma2(acc[r][3], d, ahi.y);
                }
            }
        }

        // Refill own stage for the next point. Order this warp's generic-proxy
        // tile reads before the async-proxy TMA write (fence + syncwarp), then
        // the TMA overlaps the argmax reduction below.
        const int pn = p + NBLOCKS * NWARPS;
        if (pn < NP) {
            asm volatile("fence.proxy.async.shared::cta;" ::: "memory");
            __syncwarp();
            if (lane == 0)
                tma_fill(my_tile_addr, my_mbar_addr,
                         pexp + (size_t)pn * TILE_FLOATS);
        }

        // abs-argmax over 128 segments per batch: 4-way local, 5-step shuffle.
        #pragma unroll
        for (int b = 0; b < NB; b++) {
            const int q = b >> 1;
            float bv = 0.0f, ba = -1.0f;
            #pragma unroll
            for (int r = 0; r < 4; r++) {
                const unsigned long long pa = acc[r][q];
                const float v = __uint_as_float((b & 1) ? (uint32_t)(pa >> 32) : (uint32_t)pa);
                const float a = fabsf(v);
                if (a > ba) { ba = a; bv = v; }
            }
            #pragma unroll
            for (int off = 16; off > 0; off >>= 1) {
                const float oa = __shfl_xor_sync(0xffffffffu, ba, off);
                const float ov = __shfl_xor_sync(0xffffffffu, bv, off);
                if (oa > ba) { ba = oa; bv = ov; }
            }
            if (lane == 0) out[b * NP + p] = bv;   // threshold |v|>0 is identity
        }
    }
}

extern "C" void kernel_launch(void* const* d_in, const int* in_sizes, int n_in,
                              void* d_out, int out_size) {
    (void)n_in; (void)out_size;
    const float* a0 = (const float*)d_in[0];
    const float* a1 = (const float*)d_in[1];
    const float* amp  = a0;
    const float* pexp = a1;
    if (in_sizes[0] != NB * NE) { amp = a1; pexp = a0; }

    cudaFuncSetAttribute(axon_map_kernel,
                         cudaFuncAttributeMaxDynamicSharedMemorySize, SMEM_BYTES);
    axon_map_kernel<<<NBLOCKS, THREADS, SMEM_BYTES>>>(amp, pexp, (float*)d_out);
}